// round 16
// baseline (speedup 1.0000x reference)
#include <cuda_runtime.h>
#include <cuda_fp16.h>
#include <cstdint>

#define NB 4
#define NL 4096
#define NH 16
#define ND 1024
#define Nd 64
#define MTOT (NB * NL)          // 16384
#define SEGB 512                // phase-B segment length
#define SUBA 256                // phase-A sub-segment length
#define NSUBA 14                // sub-segments covering [0, 3584)

// ---------------------------------------------------------------------------
// Device-global scratch (no allocations allowed)
// ---------------------------------------------------------------------------
__device__ __half g_qkv[(size_t)NB * NL * 3 * ND];   // fp16 qkv
__device__ float g_fst[(size_t)NSUBA * 64 * 4096];   // raw sub-segment states
__device__ float g_ust[(size_t)8 * 64 * 4096];       // raw segment-init states
__device__ __half g_sA[(size_t)MTOT * ND];           // fp16 A (x, then y)
__device__ __half g_sB1[(size_t)3 * ND * ND];        // fp16 Wqkv_w
__device__ __half g_sB2[(size_t)ND * ND];            // fp16 out_w

// ---------------------------------------------------------------------------
__device__ __forceinline__ uint32_t smem_u32(const void* p) {
    uint32_t a;
    asm("{ .reg .u64 t; cvta.to.shared.u64 t, %1; cvt.u32.u64 %0, t; }"
        : "=r"(a) : "l"(p));
    return a;
}
__device__ __forceinline__ void ldsm_x4(uint32_t* r, uint32_t addr) {
    asm volatile("ldmatrix.sync.aligned.m8n8.x4.shared.b16 {%0,%1,%2,%3}, [%4];"
                 : "=r"(r[0]), "=r"(r[1]), "=r"(r[2]), "=r"(r[3]) : "r"(addr));
}
__device__ __forceinline__ void mma_f16(float* d, const uint32_t* a, const uint32_t* b) {
    asm volatile(
        "mma.sync.aligned.m16n8k16.row.col.f32.f16.f16.f32 "
        "{%0,%1,%2,%3}, {%4,%5,%6,%7}, {%8,%9}, {%0,%1,%2,%3};"
        : "+f"(d[0]), "+f"(d[1]), "+f"(d[2]), "+f"(d[3])
        : "r"(a[0]), "r"(a[1]), "r"(a[2]), "r"(a[3]), "r"(b[0]), "r"(b[1]));
}
__device__ __forceinline__ void cp16(uint32_t saddr, const void* gaddr) {
    asm volatile("cp.async.cg.shared.global [%0], [%1], 16;" :: "r"(saddr), "l"(gaddr));
}
__device__ __forceinline__ uint64_t mul2(uint64_t a, uint64_t b) {
    uint64_t d; asm("mul.rn.f32x2 %0, %1, %2;" : "=l"(d) : "l"(a), "l"(b)); return d;
}
__device__ __forceinline__ uint64_t fma2(uint64_t a, uint64_t b, uint64_t c) {
    uint64_t d; asm("fma.rn.f32x2 %0, %1, %2, %3;" : "=l"(d) : "l"(a), "l"(b), "l"(c)); return d;
}
__device__ __forceinline__ uint64_t pack2(float lo, float hi) {
    uint64_t d;
    asm("mov.b64 %0, {%1, %2};" : "=l"(d) : "r"(__float_as_uint(lo)), "r"(__float_as_uint(hi)));
    return d;
}
__device__ __forceinline__ float hadd2(uint64_t v) {
    uint32_t lo, hi;
    asm("mov.b64 {%0, %1}, %2;" : "=r"(lo), "=r"(hi) : "l"(v));
    return __uint_as_float(lo) + __uint_as_float(hi);
}
__device__ __forceinline__ void unpack2(float& lo, float& hi, uint64_t v) {
    uint32_t l, h;
    asm("mov.b64 {%0, %1}, %2;" : "=r"(l), "=r"(h) : "l"(v));
    lo = __uint_as_float(l); hi = __uint_as_float(h);
}
__device__ __forceinline__ uint64_t h2f2(uint32_t h) {
    __half2 hh = *reinterpret_cast<__half2*>(&h);
    float2 f = __half22float2(hh);
    return pack2(f.x, f.y);
}

// ---------------------------------------------------------------------------
// Plain f32 -> f16 convert (8 elems/thread).
// ---------------------------------------------------------------------------
__global__ __launch_bounds__(256) void cvt16_kernel(
    const float* __restrict__ src, __half* __restrict__ dst, long total)
{
    long i = ((long)blockIdx.x * blockDim.x + threadIdx.x) * 8;
    if (i >= total) return;
    float4 a = *(const float4*)(src + i);
    float4 b = *(const float4*)(src + i + 4);
    __half2 o[4];
    o[0] = __floats2half2_rn(a.x, a.y);
    o[1] = __floats2half2_rn(a.z, a.w);
    o[2] = __floats2half2_rn(b.x, b.y);
    o[3] = __floats2half2_rn(b.z, b.w);
    *(uint4*)(dst + i) = *(uint4*)o;
}

// ---------------------------------------------------------------------------
// mma.sync fp16 GEMM. 128x128 CTA tile, BK=32, 3-stage cp.async,
// 60KB smem, 2 CTAs/SM. N is the C row stride; Bw/bias/C may be pre-offset.
// ---------------------------------------------------------------------------
#define GSTAGE 20480
#define GEMM_SMEM (3 * GSTAGE)

__global__ __launch_bounds__(256, 2) void gemm_mma(
    const __half* __restrict__ A, const __half* __restrict__ Bw,
    const float* __restrict__ bias, void* __restrict__ Cv,
    int N, int K, int half_out)
{
    extern __shared__ __align__(16) char dsm[];
    const uint32_t smb = smem_u32(dsm);

    const int tid = threadIdx.x;
    const int wid = tid >> 5;
    const int lane = tid & 31;
    const int wm = wid & 3;
    const int wn = wid >> 2;
    const int bm = blockIdx.y * 128;
    const int bn = blockIdx.x * 128;

    const int r0 = tid >> 2;
    const int sg = tid & 3;
    const __half* Ag = A + (size_t)(bm + r0) * K + sg * 8;
    const __half* Bg = Bw + (size_t)(bn + r0) * K + sg * 8;
    const uint32_t ldOff = (uint32_t)(r0 * 80 + sg * 16);
    const size_t rowK64 = (size_t)64 * K;

    const int l15 = lane & 15;
    const uint32_t aOff = (uint32_t)((wm * 32 + l15) * 80 + (lane >> 4) * 16);
    const int bnl = (lane & 7) + ((lane >> 4) & 1) * 8;
    const uint32_t bOff = 10240u + (uint32_t)((wn * 64 + bnl) * 80 + ((lane >> 3) & 1) * 16);

    float acc[2][8][4];
    #pragma unroll
    for (int mf = 0; mf < 2; mf++)
        #pragma unroll
        for (int nf = 0; nf < 8; nf++)
            #pragma unroll
            for (int j = 0; j < 4; j++)
                acc[mf][nf][j] = 0.0f;

    const int nch = K / 32;

    auto load_chunk = [&](int s, int ch) {
        const uint32_t stg = smb + (uint32_t)s * GSTAGE;
        const __half* Ac = Ag + (size_t)ch * 32;
        const __half* Bc = Bg + (size_t)ch * 32;
        cp16(stg + ldOff, Ac);
        cp16(stg + ldOff + 64 * 80, Ac + rowK64);
        cp16(stg + 10240 + ldOff, Bc);
        cp16(stg + 10240 + ldOff + 64 * 80, Bc + rowK64);
    };

    #pragma unroll
    for (int p = 0; p < 2; ++p) {
        load_chunk(p, p);
        asm volatile("cp.async.commit_group;" ::: "memory");
    }

    int sl = 2;
    #pragma unroll 1
    for (int c = 0; c < nch; ++c) {
        asm volatile("cp.async.wait_group 1;" ::: "memory");
        __syncthreads();

        if (c + 2 < nch) load_chunk(sl, c + 2);
        asm volatile("cp.async.commit_group;" ::: "memory");
        sl = (sl == 2) ? 0 : sl + 1;

        const uint32_t so = smb + (uint32_t)((c % 3)) * GSTAGE;
        const uint32_t aA = so + aOff;
        const uint32_t bA = so + bOff;

        #pragma unroll
        for (int ks = 0; ks < 2; ++ks) {
            uint32_t afr[2][4];
            ldsm_x4(afr[0], aA + ks * 32);
            ldsm_x4(afr[1], aA + 16 * 80 + ks * 32);
            uint32_t bfr[4][4];
            #pragma unroll
            for (int nq = 0; nq < 4; ++nq)
                ldsm_x4(bfr[nq], bA + nq * 16 * 80 + ks * 32);

            #pragma unroll
            for (int mf = 0; mf < 2; ++mf)
                #pragma unroll
                for (int nf = 0; nf < 8; ++nf)
                    mma_f16(acc[mf][nf], afr[mf], &bfr[nf >> 1][(nf & 1) * 2]);
        }
    }

    __syncthreads();

    const int erow = lane >> 2;
    const int ecol = (lane & 3) * 2;
    #pragma unroll
    for (int mf = 0; mf < 2; ++mf) {
        const int row = bm + wm * 32 + mf * 16 + erow;
        #pragma unroll
        for (int nf = 0; nf < 8; ++nf) {
            const int col = bn + wn * 64 + nf * 8 + ecol;
            float2 bb = *(const float2*)(bias + col);
            float o0x = acc[mf][nf][0] + bb.x;
            float o0y = acc[mf][nf][1] + bb.y;
            float o1x = acc[mf][nf][2] + bb.x;
            float o1y = acc[mf][nf][3] + bb.y;
            if (half_out) {
                __half* C = (__half*)Cv;
                *(__half2*)(C + (size_t)row * N + col) = __floats2half2_rn(o0x, o0y);
                *(__half2*)(C + (size_t)(row + 8) * N + col) = __floats2half2_rn(o1x, o1y);
            } else {
                float* C = (float*)Cv;
                *(float2*)(C + (size_t)row * N + col) = make_float2(o0x, o0y);
                *(float2*)(C + (size_t)(row + 8) * N + col) = make_float2(o1x, o1y);
            }
        }
    }
}

// ---------------------------------------------------------------------------
// Phase A: RAW local state over sub-segment m (256 steps, k/v only).
//   S' <- r*S' + v*k   (g deferred; applied at phaseB init via g_ust scaling)
// Block = 256 threads = 8 warps = 32 rows (half of one (b,h)).
// ---------------------------------------------------------------------------
#define PHA_SMEM 24576

__global__ __launch_bounds__(256) void stp_phaseA(
    const float* __restrict__ Lam)
{
    extern __shared__ __align__(16) __half smh[];
    const uint32_t smb = smem_u32(smh);

    const int bx = blockIdx.x;
    const int bh = bx >> 1;
    const int half = bx & 1;
    const int m = blockIdx.y;            // sub-segment 0..13
    const int b = bh >> 4;
    const int h = bh & 15;
    const int tid = threadIdx.x;
    const int wid = tid >> 5;            // 0..7
    const int lane = tid & 31;
    const int rg = lane >> 3;
    const int cg = lane & 7;
    const int row0 = half * 32;
    const int i = row0 + (wid << 2) + rg;   // row 0..63
    const int j0 = cg << 3;

    uint64_t S2[4], r2[4];
    {
        const int pbase = (h * Nd + i) * Nd + j0;
        float lv[8];
        *(float4*)(lv)     = *(const float4*)(Lam + pbase);
        *(float4*)(lv + 4) = *(const float4*)(Lam + pbase + 4);
        float rr[8];
        #pragma unroll
        for (int jj = 0; jj < 8; jj++) {
            float sgm = 1.0f / (1.0f + __expf(-lv[jj]));
            rr[jj] = 1.0f - sgm;
        }
        #pragma unroll
        for (int q = 0; q < 4; q++) {
            r2[q] = pack2(rr[2 * q], rr[2 * q + 1]);
            S2[q] = 0ull;
        }
    }

    const __half* gq = g_qkv + (size_t)b * NL * 3 * ND + h * Nd;
    const int tseg = m * SUBA;

    auto load_chunk = [&](int s, int t0) {
        #pragma unroll
        for (int it = 0; it < 2; ++it) {
            const int idx = tid + (it << 8);
            const int st = idx >> 3;
            const int sg = (idx & 7) * 8;
            const __half* src = gq + (size_t)(t0 + st) * (3 * ND) + ND + sg;
            cp16(smb + (uint32_t)s * 8192u + (uint32_t)(st * 64 + sg) * 2, src);
        }
        {
            const int st = tid >> 2;
            const int sg = (tid & 3) * 8;
            const __half* src = gq + (size_t)(t0 + st) * (3 * ND) + 2 * ND + row0 + sg;
            cp16(smb + 16384u + (uint32_t)s * 4096u + (uint32_t)(st * 32 + sg) * 2, src);
        }
        asm volatile("cp.async.commit_group;" ::: "memory");
    };

    load_chunk(0, tseg);

    const int NCA = SUBA / 64;   // 4 chunks of 64 steps
    #pragma unroll 1
    for (int c = 0; c < NCA; ++c) {
        if (c + 1 < NCA) {
            load_chunk((c + 1) & 1, tseg + (c + 1) * 64);
            asm volatile("cp.async.wait_group 1;" ::: "memory");
        } else {
            asm volatile("cp.async.wait_group 0;" ::: "memory");
        }
        __syncthreads();

        const int s = c & 1;
        const __half* ks = smh + s * 4096;
        const __half* vs = smh + 8192 + s * 2048;
        const int il = i - row0;

        #pragma unroll 4
        for (int tt = 0; tt < 64; ++tt) {
            uint4 kraw = *(const uint4*)(ks + (tt << 6) + j0);
            const float cv = __half2float(vs[(tt << 5) + il]);
            const uint64_t v2 = pack2(cv, cv);
            uint64_t k2[4] = {h2f2(kraw.x), h2f2(kraw.y), h2f2(kraw.z), h2f2(kraw.w)};
            #pragma unroll
            for (int q = 0; q < 4; ++q)
                S2[q] = fma2(r2[q], S2[q], mul2(v2, k2[q]));
        }
        __syncthreads();
    }

    float* F = g_fst + ((size_t)m * 64 + bh) * 4096 + i * 64 + j0;
    float f[8];
    #pragma unroll
    for (int q = 0; q < 4; ++q) unpack2(f[2 * q], f[2 * q + 1], S2[q]);
    *(float4*)(F)     = *(float4*)(f);
    *(float4*)(F + 4) = *(float4*)(f + 4);
}

// ---------------------------------------------------------------------------
// Combine: Horner over 14 raw sub-segment states -> raw seg-init states U'_s.
// ---------------------------------------------------------------------------
__global__ __launch_bounds__(256) void stp_combine(const float* __restrict__ Lam)
{
    const int e = blockIdx.x * 256 + threadIdx.x;   // 0..262143
    const int bh = e >> 12;
    const int idx = e & 4095;
    const int h = bh & 15;

    const float lam = Lam[h * 4096 + idx];
    const float sgm = 1.0f / (1.0f + __expf(-lam));
    float r = 1.0f - sgm;
    float r256 = r;
    #pragma unroll
    for (int q = 0; q < 8; q++) r256 *= r256;   // r^256

    float U = 0.0f;
    #pragma unroll
    for (int m = 0; m < NSUBA; ++m) {
        if (m > 0 && (m & 1) == 0)
            g_ust[((size_t)(m >> 1) * 64 + bh) * 4096 + idx] = U;
        U = r256 * U + g_fst[((size_t)m * 64 + bh) * 4096 + idx];
    }
    g_ust[((size_t)7 * 64 + bh) * 4096 + idx] = U;
}

// ---------------------------------------------------------------------------
// Phase B: full scan of segment blockIdx.y (512 steps).
// Init: u0 = W + g * U'_raw   (g applied here, once).
// Block = 256 threads = 32 rows (half of one (b,h)). grid (128, 8).
// ---------------------------------------------------------------------------
#define PHB_SMEM 20480

__global__ __launch_bounds__(256) void stp_phaseB(
    const float* __restrict__ Wst,
    const float* __restrict__ Lam,
    const float* __restrict__ Gam)
{
    extern __shared__ __align__(16) __half smh[];
    const uint32_t smb = smem_u32(smh);

    const int bx = blockIdx.x;
    const int bh = bx >> 1;
    const int half = bx & 1;
    const int p = blockIdx.y;            // segment 0..7
    const int b = bh >> 4;
    const int h = bh & 15;
    const int tid = threadIdx.x;
    const int wid = tid >> 5;            // 0..7
    const int lane = tid & 31;
    const int rg = lane >> 3;
    const int cg = lane & 7;
    const int row0 = half * 32;
    const int i = row0 + (wid << 2) + rg;   // row 0..63
    const int j0 = cg << 3;

    uint64_t u2[4], r2[4], g2[4], cw2[4];
    {
        const int pbase = (h * Nd + i) * Nd + j0;
        float wv[8], lv[8], gv[8];
        *(float4*)(wv)     = *(const float4*)(Wst + pbase);
        *(float4*)(wv + 4) = *(const float4*)(Wst + pbase + 4);
        *(float4*)(lv)     = *(const float4*)(Lam + pbase);
        *(float4*)(lv + 4) = *(const float4*)(Lam + pbase + 4);
        *(float4*)(gv)     = *(const float4*)(Gam + pbase);
        *(float4*)(gv + 4) = *(const float4*)(Gam + pbase + 4);
        float rr[8], gg[8], cc[8];
        #pragma unroll
        for (int jj = 0; jj < 8; jj++) {
            float sgm = 1.0f / (1.0f + __expf(-lv[jj]));
            rr[jj] = 1.0f - sgm;
            cc[jj] = sgm * wv[jj];
            gg[jj] = gv[jj] * 0.125f;
        }

        float U[8] = {0, 0, 0, 0, 0, 0, 0, 0};
        if (p > 0) {
            const float* Up = g_ust + ((size_t)p * 64 + bh) * 4096 + i * 64 + j0;
            *(float4*)(U)     = *(const float4*)(Up);
            *(float4*)(U + 4) = *(const float4*)(Up + 4);
        }

        #pragma unroll
        for (int q = 0; q < 4; q++) {
            u2[q]  = pack2(wv[2 * q] + gg[2 * q] * U[2 * q],
                           wv[2 * q + 1] + gg[2 * q + 1] * U[2 * q + 1]);
            r2[q]  = pack2(rr[2 * q], rr[2 * q + 1]);
            g2[q]  = pack2(gg[2 * q], gg[2 * q + 1]);
            cw2[q] = pack2(cc[2 * q], cc[2 * q + 1]);
        }
    }

    const __half* gq = g_qkv + (size_t)b * NL * 3 * ND + h * Nd;
    __half* ybase = g_sA + (size_t)(b * NL) * ND + (h * 64 + i);
    const int tseg = p * SEGB;

    auto load_chunk = [&](int s, int t0) {
        {
            const int st = tid >> 3;
            const int sg = (tid & 7) * 8;
            const __half* src = gq + (size_t)(t0 + st) * (3 * ND) + sg;
            const uint32_t o = (uint32_t)(st * 64 + sg) * 2 + (uint32_t)s * 4096u;
            cp16(smb + o, src);               // q
            cp16(smb + 8192u + o, src + ND);  // k
        }
        if (tid < 128) {
            const int st = tid >> 2;
            const int sg = (tid & 3) * 8;
            const __half* src = gq + (size_t)(t0 + st) * (3 * ND) + 2 * ND + row0 + sg;
            cp16(smb + 16384u + (uint32_t)s * 2048u + (uint32_t)(st * 32 + sg) * 2, src);
        }
        asm volatile("cp.async.commit_group;" ::: "memory");
    };

    load_chunk(0, tseg);

    const int NCB = SEGB / 32;   // 16 chunks of 32 steps
    #pragma unroll 1
    for (int c = 0; c < NCB; ++c) {
        if (c + 1 < NCB) {
            load_chunk((c + 1) & 1, tseg + (c + 1) * 32);
            asm volatile("cp.async.wait_group 1;" ::: "memory");
        } else {
            asm volatile("cp.async.wait_group 0;" ::: "memory");
        }
        __syncthreads();

        const int s = c & 1;
        const __half* qs = smh + s * 2048;
        const __half* ks = smh + 4096 + s * 2048;
        const __half* vs = smh + 8192 + s * 1024;
        const int il = i - row0;

        #pragma unroll 1
        for (int tt0 = 0; tt0 < 32; tt0 += 8) {
            float yps[8];
            #pragma unroll
            for (int ss = 0; ss < 8; ++ss) {
                const int tt = tt0 + ss;
                uint4 qraw = *(const uint4*)(qs + (tt << 6) + j0);
                uint4 kraw = *(const uint4*)(ks + (tt << 6) + j0);
                const float cv = __half2float(vs[(tt << 5) + il]);
                const uint64_t v2 = pack2(cv, cv);
                uint64_t q2[4] = {h2f2(qraw.x), h2f2(qraw.y), h2f2(qraw.z), h2f2(qraw.w)};
                uint64_t k2[4] = {h2f2(kraw.x), h2f2(kraw.y), h2f2(kraw.z), h2f2(kraw.w)};

                uint64_t acc = 0ull;
                #pragma unroll
                for (int q = 0; q < 4; ++q) {
                    uint64_t vk = mul2(v2, k2[q]);
                    uint64_t tmp = fma2(g2[q], vk, cw2[q]);
                    u2[q] = fma2(r2[q], u2[q], tmp);
                    acc = fma2(u2[q], q2[q], acc);
                }
                yps[ss] = hadd2(acc);
            }

            #pragma unroll
            for (int ss = 0; ss < 8; ++ss) yps[ss] += __shfl_xor_sync(0xffffffffu, yps[ss], 1);
            #pragma unroll
            for (int ss = 0; ss < 8; ++ss) yps[ss] += __shfl_xor_sync(0xffffffffu, yps[ss], 2);
            #pragma unroll
            for (int ss = 0; ss < 8; ++ss) yps[ss] += __shfl_xor_sync(0xffffffffu, yps[ss], 4);

            if (cg == 0) {
                const size_t t0g = (size_t)tseg + c * 32 + tt0;
                #pragma unroll
                for (int ss = 0; ss < 8; ++ss)
                    ybase[(t0g + ss) * ND] = __float2half_rn(yps[ss]);
            }
        }
        __syncthreads();
    }
}

// ---------------------------------------------------------------------------

extern "C" void kernel_launch(void* const* d_in, const int* in_sizes, int n_in,
                              void* d_out, int out_size)
{
    const float* x          = (const float*)d_in[0];
    const float* Wqkv_w     = (const float*)d_in[1];
    const float* Wqkv_b     = (const float*)d_in[2];
    const float* out_w      = (const float*)d_in[3];
    const float* out_b      = (const float*)d_in[4];
    const float* W_static   = (const float*)d_in[5];
    const float* Lambda_raw = (const float*)d_in[6];
    const float* Gamma      = (const float*)d_in[7];

    __half* qkv = nullptr;
    __half *sA = nullptr, *sB1 = nullptr, *sB2 = nullptr;
    cudaGetSymbolAddress((void**)&qkv, g_qkv);
    cudaGetSymbolAddress((void**)&sA, g_sA);
    cudaGetSymbolAddress((void**)&sB1, g_sB1);
    cudaGetSymbolAddress((void**)&sB2, g_sB2);

    static cudaStream_t s1 = nullptr;
    static cudaEvent_t e0 = nullptr, eKV = nullptr, eQ = nullptr;
    static bool attr_set = false;
    if (!attr_set) {
        cudaFuncSetAttribute(gemm_mma, cudaFuncAttributeMaxDynamicSharedMemorySize, GEMM_SMEM);
        cudaFuncSetAttribute(stp_phaseA, cudaFuncAttributeMaxDynamicSharedMemorySize, PHA_SMEM);
        cudaFuncSetAttribute(stp_phaseB, cudaFuncAttributeMaxDynamicSharedMemorySize, PHB_SMEM);
        cudaStreamCreateWithFlags(&s1, cudaStreamNonBlocking);
        cudaEventCreateWithFlags(&e0, cudaEventDisableTiming);
        cudaEventCreateWithFlags(&eKV, cudaEventDisableTiming);
        cudaEventCreateWithFlags(&eQ, cudaEventDisableTiming);
        attr_set = true;
    }

    const long nx = (long)MTOT * ND;
    const long nw1 = (long)3 * ND * ND;
    const long nw2 = (long)ND * ND;

    // fork side stream into the capture DAG
    cudaEventRecord(e0, 0);
    cudaStreamWaitEvent(s1, e0, 0);

    // s1: convert out_w
    cvt16_kernel<<<(unsigned)((nw2 / 8 + 255) / 256), 256, 0, s1>>>(out_w, sB2, nw2);

    // main: convert x, Wqkv_w
    cvt16_kernel<<<(unsigned)((nx / 8 + 255) / 256), 256>>>(x, sA, nx);
    cvt16_kernel<<<(unsigned)((nw1 / 8 + 255) / 256), 256>>>(Wqkv_w, sB1, nw1);

    // main: kv-GEMM (qkv cols 1024..3071)
    gemm_mma<<<dim3(16, 128), 256, GEMM_SMEM>>>(
        sA, sB1 + (size_t)ND * ND, Wqkv_b + ND, qkv + ND, 3 * ND, ND, 1);
    cudaEventRecord(eKV, 0);

    // s1: q-GEMM (cols 0..1023), overlaps phaseA/combine on main
    cudaStreamWaitEvent(s1, eKV, 0);
    gemm_mma<<<dim3(8, 128), 256, GEMM_SMEM, s1>>>(
        sA, sB1, Wqkv_b, qkv, 3 * ND, ND, 1);
    cudaEventRecord(eQ, s1);

    // main: phase A (raw states, k/v only) + combine
    stp_phaseA<<<dim3(NB * NH * 2, NSUBA), 256, PHA_SMEM>>>(Lambda_raw);
    stp_combine<<<1024, 256>>>(Lambda_raw);

    // join: phaseB needs q (and overwrites sA which q-GEMM reads)
    cudaStreamWaitEvent(0, eQ, 0);
    stp_phaseB<<<dim3(NB * NH * 2, 8), 256, PHB_SMEM>>>(W_static, Lambda_raw, Gamma);

    // main: out = y @ out_w^T + b (f32)
    gemm_mma<<<dim3(8, 128), 256, GEMM_SMEM>>>(
        sA, sB2, out_b, d_out, ND, ND, 0);
}

// round 17
// speedup vs baseline: 1.5811x; 1.5811x over previous
#include <cuda_runtime.h>
#include <cuda_fp16.h>
#include <cstdint>

#define NB 4
#define NL 4096
#define NH 16
#define ND 1024
#define Nd 64
#define MTOT (NB * NL)          // 16384
#define SEGB 512                // phase-B segment length
#define SUBA 256                // phase-A sub-segment length
#define NSUBA 14                // sub-segments covering [0, 3584)

// ---------------------------------------------------------------------------
// Device-global scratch (no allocations allowed)
// ---------------------------------------------------------------------------
__device__ __half g_qkv[(size_t)NB * NL * 3 * ND];   // fp16 qkv
__device__ float g_fst[(size_t)NSUBA * 64 * 4096];   // raw sub-segment states
__device__ float g_ust[(size_t)8 * 64 * 4096];       // raw segment-init states
__device__ __half g_sA[(size_t)MTOT * ND];           // fp16 A (x, then y)
__device__ __half g_sB1[(size_t)3 * ND * ND];        // fp16 Wqkv_w
__device__ __half g_sB2[(size_t)ND * ND];            // fp16 out_w

// ---------------------------------------------------------------------------
__device__ __forceinline__ uint32_t smem_u32(const void* p) {
    uint32_t a;
    asm("{ .reg .u64 t; cvta.to.shared.u64 t, %1; cvt.u32.u64 %0, t; }"
        : "=r"(a) : "l"(p));
    return a;
}
__device__ __forceinline__ void ldsm_x4(uint32_t* r, uint32_t addr) {
    asm volatile("ldmatrix.sync.aligned.m8n8.x4.shared.b16 {%0,%1,%2,%3}, [%4];"
                 : "=r"(r[0]), "=r"(r[1]), "=r"(r[2]), "=r"(r[3]) : "r"(addr));
}
__device__ __forceinline__ void mma_f16(float* d, const uint32_t* a, const uint32_t* b) {
    asm volatile(
        "mma.sync.aligned.m16n8k16.row.col.f32.f16.f16.f32 "
        "{%0,%1,%2,%3}, {%4,%5,%6,%7}, {%8,%9}, {%0,%1,%2,%3};"
        : "+f"(d[0]), "+f"(d[1]), "+f"(d[2]), "+f"(d[3])
        : "r"(a[0]), "r"(a[1]), "r"(a[2]), "r"(a[3]), "r"(b[0]), "r"(b[1]));
}
__device__ __forceinline__ void cp16(uint32_t saddr, const void* gaddr) {
    asm volatile("cp.async.cg.shared.global [%0], [%1], 16;" :: "r"(saddr), "l"(gaddr));
}
__device__ __forceinline__ uint64_t mul2(uint64_t a, uint64_t b) {
    uint64_t d; asm("mul.rn.f32x2 %0, %1, %2;" : "=l"(d) : "l"(a), "l"(b)); return d;
}
__device__ __forceinline__ uint64_t fma2(uint64_t a, uint64_t b, uint64_t c) {
    uint64_t d; asm("fma.rn.f32x2 %0, %1, %2, %3;" : "=l"(d) : "l"(a), "l"(b), "l"(c)); return d;
}
__device__ __forceinline__ uint64_t pack2(float lo, float hi) {
    uint64_t d;
    asm("mov.b64 %0, {%1, %2};" : "=l"(d) : "r"(__float_as_uint(lo)), "r"(__float_as_uint(hi)));
    return d;
}
__device__ __forceinline__ float hadd2(uint64_t v) {
    uint32_t lo, hi;
    asm("mov.b64 {%0, %1}, %2;" : "=r"(lo), "=r"(hi) : "l"(v));
    return __uint_as_float(lo) + __uint_as_float(hi);
}
__device__ __forceinline__ void unpack2(float& lo, float& hi, uint64_t v) {
    uint32_t l, h;
    asm("mov.b64 {%0, %1}, %2;" : "=r"(l), "=r"(h) : "l"(v));
    lo = __uint_as_float(l); hi = __uint_as_float(h);
}
__device__ __forceinline__ uint64_t h2f2(uint32_t h) {
    __half2 hh = *reinterpret_cast<__half2*>(&h);
    float2 f = __half22float2(hh);
    return pack2(f.x, f.y);
}

// ---------------------------------------------------------------------------
// Plain f32 -> f16 convert (8 elems/thread).
// ---------------------------------------------------------------------------
__global__ __launch_bounds__(256) void cvt16_kernel(
    const float* __restrict__ src, __half* __restrict__ dst, long total)
{
    long i = ((long)blockIdx.x * blockDim.x + threadIdx.x) * 8;
    if (i >= total) return;
    float4 a = *(const float4*)(src + i);
    float4 b = *(const float4*)(src + i + 4);
    __half2 o[4];
    o[0] = __floats2half2_rn(a.x, a.y);
    o[1] = __floats2half2_rn(a.z, a.w);
    o[2] = __floats2half2_rn(b.x, b.y);
    o[3] = __floats2half2_rn(b.z, b.w);
    *(uint4*)(dst + i) = *(uint4*)o;
}

// ---------------------------------------------------------------------------
// mma.sync fp16 GEMM. 128x128 CTA tile, BK=32, 3-stage cp.async,
// 60KB smem, 2 CTAs/SM. N is the C row stride; Bw/bias/C may be pre-offset.
// ---------------------------------------------------------------------------
#define GSTAGE 20480
#define GEMM_SMEM (3 * GSTAGE)

__global__ __launch_bounds__(256, 2) void gemm_mma(
    const __half* __restrict__ A, const __half* __restrict__ Bw,
    const float* __restrict__ bias, void* __restrict__ Cv,
    int N, int K, int half_out)
{
    extern __shared__ __align__(16) char dsm[];
    const uint32_t smb = smem_u32(dsm);

    const int tid = threadIdx.x;
    const int wid = tid >> 5;
    const int lane = tid & 31;
    const int wm = wid & 3;
    const int wn = wid >> 2;
    const int bm = blockIdx.y * 128;
    const int bn = blockIdx.x * 128;

    const int r0 = tid >> 2;
    const int sg = tid & 3;
    const __half* Ag = A + (size_t)(bm + r0) * K + sg * 8;
    const __half* Bg = Bw + (size_t)(bn + r0) * K + sg * 8;
    const uint32_t ldOff = (uint32_t)(r0 * 80 + sg * 16);
    const size_t rowK64 = (size_t)64 * K;

    const int l15 = lane & 15;
    const uint32_t aOff = (uint32_t)((wm * 32 + l15) * 80 + (lane >> 4) * 16);
    const int bnl = (lane & 7) + ((lane >> 4) & 1) * 8;
    const uint32_t bOff = 10240u + (uint32_t)((wn * 64 + bnl) * 80 + ((lane >> 3) & 1) * 16);

    float acc[2][8][4];
    #pragma unroll
    for (int mf = 0; mf < 2; mf++)
        #pragma unroll
        for (int nf = 0; nf < 8; nf++)
            #pragma unroll
            for (int j = 0; j < 4; j++)
                acc[mf][nf][j] = 0.0f;

    const int nch = K / 32;

    auto load_chunk = [&](int s, int ch) {
        const uint32_t stg = smb + (uint32_t)s * GSTAGE;
        const __half* Ac = Ag + (size_t)ch * 32;
        const __half* Bc = Bg + (size_t)ch * 32;
        cp16(stg + ldOff, Ac);
        cp16(stg + ldOff + 64 * 80, Ac + rowK64);
        cp16(stg + 10240 + ldOff, Bc);
        cp16(stg + 10240 + ldOff + 64 * 80, Bc + rowK64);
    };

    #pragma unroll
    for (int p = 0; p < 2; ++p) {
        load_chunk(p, p);
        asm volatile("cp.async.commit_group;" ::: "memory");
    }

    int sl = 2;
    #pragma unroll 1
    for (int c = 0; c < nch; ++c) {
        asm volatile("cp.async.wait_group 1;" ::: "memory");
        __syncthreads();

        if (c + 2 < nch) load_chunk(sl, c + 2);
        asm volatile("cp.async.commit_group;" ::: "memory");
        sl = (sl == 2) ? 0 : sl + 1;

        const uint32_t so = smb + (uint32_t)((c % 3)) * GSTAGE;
        const uint32_t aA = so + aOff;
        const uint32_t bA = so + bOff;

        #pragma unroll
        for (int ks = 0; ks < 2; ++ks) {
            uint32_t afr[2][4];
            ldsm_x4(afr[0], aA + ks * 32);
            ldsm_x4(afr[1], aA + 16 * 80 + ks * 32);
            uint32_t bfr[4][4];
            #pragma unroll
            for (int nq = 0; nq < 4; ++nq)
                ldsm_x4(bfr[nq], bA + nq * 16 * 80 + ks * 32);

            #pragma unroll
            for (int mf = 0; mf < 2; ++mf)
                #pragma unroll
                for (int nf = 0; nf < 8; ++nf)
                    mma_f16(acc[mf][nf], afr[mf], &bfr[nf >> 1][(nf & 1) * 2]);
        }
    }

    __syncthreads();

    const int erow = lane >> 2;
    const int ecol = (lane & 3) * 2;
    #pragma unroll
    for (int mf = 0; mf < 2; ++mf) {
        const int row = bm + wm * 32 + mf * 16 + erow;
        #pragma unroll
        for (int nf = 0; nf < 8; ++nf) {
            const int col = bn + wn * 64 + nf * 8 + ecol;
            float2 bb = *(const float2*)(bias + col);
            float o0x = acc[mf][nf][0] + bb.x;
            float o0y = acc[mf][nf][1] + bb.y;
            float o1x = acc[mf][nf][2] + bb.x;
            float o1y = acc[mf][nf][3] + bb.y;
            if (half_out) {
                __half* C = (__half*)Cv;
                *(__half2*)(C + (size_t)row * N + col) = __floats2half2_rn(o0x, o0y);
                *(__half2*)(C + (size_t)(row + 8) * N + col) = __floats2half2_rn(o1x, o1y);
            } else {
                float* C = (float*)Cv;
                *(float2*)(C + (size_t)row * N + col) = make_float2(o0x, o0y);
                *(float2*)(C + (size_t)(row + 8) * N + col) = make_float2(o1x, o1y);
            }
        }
    }
}

// ---------------------------------------------------------------------------
// Phase A: RAW local state over sub-segment m (256 steps, k/v only).
//   S' <- r*S' + v*k   (g deferred; applied at phaseB init)
// Block = 256 threads = 8 warps = 32 rows (half of one (b,h)).
// ---------------------------------------------------------------------------
#define PHA_SMEM 24576

__global__ __launch_bounds__(256) void stp_phaseA(
    const float* __restrict__ Lam)
{
    extern __shared__ __align__(16) __half smh[];
    const uint32_t smb = smem_u32(smh);

    const int bx = blockIdx.x;
    const int bh = bx >> 1;
    const int half = bx & 1;
    const int m = blockIdx.y;            // sub-segment 0..13
    const int b = bh >> 4;
    const int h = bh & 15;
    const int tid = threadIdx.x;
    const int wid = tid >> 5;            // 0..7
    const int lane = tid & 31;
    const int rg = lane >> 3;
    const int cg = lane & 7;
    const int row0 = half * 32;
    const int i = row0 + (wid << 2) + rg;   // row 0..63
    const int j0 = cg << 3;

    uint64_t S2[4], r2[4];
    {
        const int pbase = (h * Nd + i) * Nd + j0;
        float lv[8];
        *(float4*)(lv)     = *(const float4*)(Lam + pbase);
        *(float4*)(lv + 4) = *(const float4*)(Lam + pbase + 4);
        float rr[8];
        #pragma unroll
        for (int jj = 0; jj < 8; jj++) {
            float sgm = 1.0f / (1.0f + __expf(-lv[jj]));
            rr[jj] = 1.0f - sgm;
        }
        #pragma unroll
        for (int q = 0; q < 4; q++) {
            r2[q] = pack2(rr[2 * q], rr[2 * q + 1]);
            S2[q] = 0ull;
        }
    }

    const __half* gq = g_qkv + (size_t)b * NL * 3 * ND + h * Nd;
    const int tseg = m * SUBA;

    auto load_chunk = [&](int s, int t0) {
        #pragma unroll
        for (int it = 0; it < 2; ++it) {
            const int idx = tid + (it << 8);
            const int st = idx >> 3;
            const int sg = (idx & 7) * 8;
            const __half* src = gq + (size_t)(t0 + st) * (3 * ND) + ND + sg;
            cp16(smb + (uint32_t)s * 8192u + (uint32_t)(st * 64 + sg) * 2, src);
        }
        {
            const int st = tid >> 2;
            const int sg = (tid & 3) * 8;
            const __half* src = gq + (size_t)(t0 + st) * (3 * ND) + 2 * ND + row0 + sg;
            cp16(smb + 16384u + (uint32_t)s * 4096u + (uint32_t)(st * 32 + sg) * 2, src);
        }
        asm volatile("cp.async.commit_group;" ::: "memory");
    };

    load_chunk(0, tseg);

    const int NCA = SUBA / 64;   // 4 chunks of 64 steps
    #pragma unroll 1
    for (int c = 0; c < NCA; ++c) {
        if (c + 1 < NCA) {
            load_chunk((c + 1) & 1, tseg + (c + 1) * 64);
            asm volatile("cp.async.wait_group 1;" ::: "memory");
        } else {
            asm volatile("cp.async.wait_group 0;" ::: "memory");
        }
        __syncthreads();

        const int s = c & 1;
        const __half* ks = smh + s * 4096;
        const __half* vs = smh + 8192 + s * 2048;
        const int il = i - row0;

        #pragma unroll 4
        for (int tt = 0; tt < 64; ++tt) {
            uint4 kraw = *(const uint4*)(ks + (tt << 6) + j0);
            const float cv = __half2float(vs[(tt << 5) + il]);
            const uint64_t v2 = pack2(cv, cv);
            uint64_t k2[4] = {h2f2(kraw.x), h2f2(kraw.y), h2f2(kraw.z), h2f2(kraw.w)};
            #pragma unroll
            for (int q = 0; q < 4; ++q)
                S2[q] = fma2(r2[q], S2[q], mul2(v2, k2[q]));
        }
        __syncthreads();
    }

    float* F = g_fst + ((size_t)m * 64 + bh) * 4096 + i * 64 + j0;
    float f[8];
    #pragma unroll
    for (int q = 0; q < 4; ++q) unpack2(f[2 * q], f[2 * q + 1], S2[q]);
    *(float4*)(F)     = *(float4*)(f);
    *(float4*)(F + 4) = *(float4*)(f + 4);
}

// ---------------------------------------------------------------------------
// Combine: Horner over 14 raw sub-segment states -> raw seg-init states U'_s.
// ---------------------------------------------------------------------------
__global__ __launch_bounds__(256) void stp_combine(const float* __restrict__ Lam)
{
    const int e = blockIdx.x * 256 + threadIdx.x;   // 0..262143
    const int bh = e >> 12;
    const int idx = e & 4095;
    const int h = bh & 15;

    const float lam = Lam[h * 4096 + idx];
    const float sgm = 1.0f / (1.0f + __expf(-lam));
    float r = 1.0f - sgm;
    float r256 = r;
    #pragma unroll
    for (int q = 0; q < 8; q++) r256 *= r256;   // r^256

    float U = 0.0f;
    #pragma unroll
    for (int m = 0; m < NSUBA; ++m) {
        if (m > 0 && (m & 1) == 0)
            g_ust[((size_t)(m >> 1) * 64 + bh) * 4096 + idx] = U;
        U = r256 * U + g_fst[((size_t)m * 64 + bh) * 4096 + idx];
    }
    g_ust[((size_t)7 * 64 + bh) * 4096 + idx] = U;
}

// ---------------------------------------------------------------------------
// Phase B: full scan of segment blockIdx.y (512 steps).
// Init: u0 = W + g * U'_raw   (g applied here, once).
// Block = 256 threads = 32 rows (half of one (b,h)). grid (128, 8).
// ---------------------------------------------------------------------------
#define PHB_SMEM 20480

__global__ __launch_bounds__(256) void stp_phaseB(
    const float* __restrict__ Wst,
    const float* __restrict__ Lam,
    const float* __restrict__ Gam)
{
    extern __shared__ __align__(16) __half smh[];
    const uint32_t smb = smem_u32(smh);

    const int bx = blockIdx.x;
    const int bh = bx >> 1;
    const int half = bx & 1;
    const int p = blockIdx.y;            // segment 0..7
    const int b = bh >> 4;
    const int h = bh & 15;
    const int tid = threadIdx.x;
    const int wid = tid >> 5;            // 0..7
    const int lane = tid & 31;
    const int rg = lane >> 3;
    const int cg = lane & 7;
    const int row0 = half * 32;
    const int i = row0 + (wid << 2) + rg;   // row 0..63
    const int j0 = cg << 3;

    uint64_t u2[4], r2[4], g2[4], cw2[4];
    {
        const int pbase = (h * Nd + i) * Nd + j0;
        float wv[8], lv[8], gv[8];
        *(float4*)(wv)     = *(const float4*)(Wst + pbase);
        *(float4*)(wv + 4) = *(const float4*)(Wst + pbase + 4);
        *(float4*)(lv)     = *(const float4*)(Lam + pbase);
        *(float4*)(lv + 4) = *(const float4*)(Lam + pbase + 4);
        *(float4*)(gv)     = *(const float4*)(Gam + pbase);
        *(float4*)(gv + 4) = *(const float4*)(Gam + pbase + 4);
        float rr[8], gg[8], cc[8];
        #pragma unroll
        for (int jj = 0; jj < 8; jj++) {
            float sgm = 1.0f / (1.0f + __expf(-lv[jj]));
            rr[jj] = 1.0f - sgm;
            cc[jj] = sgm * wv[jj];
            gg[jj] = gv[jj] * 0.125f;
        }

        float U[8] = {0, 0, 0, 0, 0, 0, 0, 0};
        if (p > 0) {
            const float* Up = g_ust + ((size_t)p * 64 + bh) * 4096 + i * 64 + j0;
            *(float4*)(U)     = *(const float4*)(Up);
            *(float4*)(U + 4) = *(const float4*)(Up + 4);
        }

        #pragma unroll
        for (int q = 0; q < 4; q++) {
            u2[q]  = pack2(wv[2 * q] + gg[2 * q] * U[2 * q],
                           wv[2 * q + 1] + gg[2 * q + 1] * U[2 * q + 1]);
            r2[q]  = pack2(rr[2 * q], rr[2 * q + 1]);
            g2[q]  = pack2(gg[2 * q], gg[2 * q + 1]);
            cw2[q] = pack2(cc[2 * q], cc[2 * q + 1]);
        }
    }

    const __half* gq = g_qkv + (size_t)b * NL * 3 * ND + h * Nd;
    __half* ybase = g_sA + (size_t)(b * NL) * ND + (h * 64 + i);
    const int tseg = p * SEGB;

    auto load_chunk = [&](int s, int t0) {
        {
            const int st = tid >> 3;
            const int sg = (tid & 7) * 8;
            const __half* src = gq + (size_t)(t0 + st) * (3 * ND) + sg;
            const uint32_t o = (uint32_t)(st * 64 + sg) * 2 + (uint32_t)s * 4096u;
            cp16(smb + o, src);               // q
            cp16(smb + 8192u + o, src + ND);  // k
        }
        if (tid < 128) {
            const int st = tid >> 2;
            const int sg = (tid & 3) * 8;
            const __half* src = gq + (size_t)(t0 + st) * (3 * ND) + 2 * ND + row0 + sg;
            cp16(smb + 16384u + (uint32_t)s * 2048u + (uint32_t)(st * 32 + sg) * 2, src);
        }
        asm volatile("cp.async.commit_group;" ::: "memory");
    };

    load_chunk(0, tseg);

    const int NCB = SEGB / 32;   // 16 chunks of 32 steps
    #pragma unroll 1
    for (int c = 0; c < NCB; ++c) {
        if (c + 1 < NCB) {
            load_chunk((c + 1) & 1, tseg + (c + 1) * 32);
            asm volatile("cp.async.wait_group 1;" ::: "memory");
        } else {
            asm volatile("cp.async.wait_group 0;" ::: "memory");
        }
        __syncthreads();

        const int s = c & 1;
        const __half* qs = smh + s * 2048;
        const __half* ks = smh + 4096 + s * 2048;
        const __half* vs = smh + 8192 + s * 1024;
        const int il = i - row0;

        #pragma unroll 1
        for (int tt0 = 0; tt0 < 32; tt0 += 8) {
            float yps[8];
            #pragma unroll
            for (int ss = 0; ss < 8; ++ss) {
                const int tt = tt0 + ss;
                uint4 qraw = *(const uint4*)(qs + (tt << 6) + j0);
                uint4 kraw = *(const uint4*)(ks + (tt << 6) + j0);
                const float cv = __half2float(vs[(tt << 5) + il]);
                const uint64_t v2 = pack2(cv, cv);
                uint64_t q2[4] = {h2f2(qraw.x), h2f2(qraw.y), h2f2(qraw.z), h2f2(qraw.w)};
                uint64_t k2[4] = {h2f2(kraw.x), h2f2(kraw.y), h2f2(kraw.z), h2f2(kraw.w)};

                uint64_t acc = 0ull;
                #pragma unroll
                for (int q = 0; q < 4; ++q) {
                    uint64_t vk = mul2(v2, k2[q]);
                    uint64_t tmp = fma2(g2[q], vk, cw2[q]);
                    u2[q] = fma2(r2[q], u2[q], tmp);
                    acc = fma2(u2[q], q2[q], acc);
                }
                yps[ss] = hadd2(acc);
            }

            #pragma unroll
            for (int ss = 0; ss < 8; ++ss) yps[ss] += __shfl_xor_sync(0xffffffffu, yps[ss], 1);
            #pragma unroll
            for (int ss = 0; ss < 8; ++ss) yps[ss] += __shfl_xor_sync(0xffffffffu, yps[ss], 2);
            #pragma unroll
            for (int ss = 0; ss < 8; ++ss) yps[ss] += __shfl_xor_sync(0xffffffffu, yps[ss], 4);

            if (cg == 0) {
                const size_t t0g = (size_t)tseg + c * 32 + tt0;
                #pragma unroll
                for (int ss = 0; ss < 8; ++ss)
                    ybase[(t0g + ss) * ND] = __float2half_rn(yps[ss]);
            }
        }
        __syncthreads();
    }
}

// ---------------------------------------------------------------------------

extern "C" void kernel_launch(void* const* d_in, const int* in_sizes, int n_in,
                              void* d_out, int out_size)
{
    const float* x          = (const float*)d_in[0];
    const float* Wqkv_w     = (const float*)d_in[1];
    const float* Wqkv_b     = (const float*)d_in[2];
    const float* out_w      = (const float*)d_in[3];
    const float* out_b      = (const float*)d_in[4];
    const float* W_static   = (const float*)d_in[5];
    const float* Lambda_raw = (const float*)d_in[6];
    const float* Gamma      = (const float*)d_in[7];

    __half* qkv = nullptr;
    __half *sA = nullptr, *sB1 = nullptr, *sB2 = nullptr;
    cudaGetSymbolAddress((void**)&qkv, g_qkv);
    cudaGetSymbolAddress((void**)&sA, g_sA);
    cudaGetSymbolAddress((void**)&sB1, g_sB1);
    cudaGetSymbolAddress((void**)&sB2, g_sB2);

    static cudaStream_t s1 = nullptr;
    static cudaEvent_t e0 = nullptr, eKV = nullptr, eQ = nullptr;
    static bool attr_set = false;
    if (!attr_set) {
        cudaFuncSetAttribute(gemm_mma, cudaFuncAttributeMaxDynamicSharedMemorySize, GEMM_SMEM);
        cudaFuncSetAttribute(stp_phaseA, cudaFuncAttributeMaxDynamicSharedMemorySize, PHA_SMEM);
        cudaFuncSetAttribute(stp_phaseB, cudaFuncAttributeMaxDynamicSharedMemorySize, PHB_SMEM);
        cudaStreamCreateWithFlags(&s1, cudaStreamNonBlocking);
        cudaEventCreateWithFlags(&e0, cudaEventDisableTiming);
        cudaEventCreateWithFlags(&eKV, cudaEventDisableTiming);
        cudaEventCreateWithFlags(&eQ, cudaEventDisableTiming);
        attr_set = true;
    }

    const long nx = (long)MTOT * ND;
    const long nw1 = (long)3 * ND * ND;
    const long nw2 = (long)ND * ND;

    // fork side stream into the capture DAG
    cudaEventRecord(e0, 0);
    cudaStreamWaitEvent(s1, e0, 0);

    // s1: convert out_w
    cvt16_kernel<<<(unsigned)((nw2 / 8 + 255) / 256), 256, 0, s1>>>(out_w, sB2, nw2);

    // main: convert x, Wqkv_w
    cvt16_kernel<<<(unsigned)((nx / 8 + 255) / 256), 256>>>(x, sA, nx);
    cvt16_kernel<<<(unsigned)((nw1 / 8 + 255) / 256), 256>>>(Wqkv_w, sB1, nw1);

    // main: kv-GEMM (qkv cols 1024..3071)
    gemm_mma<<<dim3(16, 128), 256, GEMM_SMEM>>>(
        sA, sB1 + (size_t)ND * ND, Wqkv_b + ND, qkv + ND, 3 * ND, ND, 1);
    cudaEventRecord(eKV, 0);

    // s1: q-GEMM (cols 0..1023), overlaps phaseA/combine on main
    cudaStreamWaitEvent(s1, eKV, 0);
    gemm_mma<<<dim3(8, 128), 256, GEMM_SMEM, s1>>>(
        sA, sB1, Wqkv_b, qkv, 3 * ND, ND, 1);
    cudaEventRecord(eQ, s1);

    // main: phase A (raw states, k/v only) + combine
    stp_phaseA<<<dim3(NB * NH * 2, NSUBA), 256, PHA_SMEM>>>(Lambda_raw);
    stp_combine<<<1024, 256>>>(Lambda_raw);

    // join: phaseB needs q (and overwrites sA which q-GEMM reads)
    cudaStreamWaitEvent(0, eQ, 0);
    stp_phaseB<<<dim3(NB * NH * 2, 8), 256, PHB_SMEM>>>(W_static, Lambda_raw, Gamma);

    // main: out = y @ out_w^T + b (f32)
    gemm_mma<<<dim3(8, 128), 256, GEMM_SMEM>>>(
        sA, sB2, out_b, d_out, ND, ND, 0);
}